// round 16
// baseline (speedup 1.0000x reference)
#include <cuda_runtime.h>
#include <cuda_bf16.h>
#include <cuda_fp16.h>
#include <cstdint>

#define EPSV 1e-5f

#define NB 32
#define NC 512
#define ND 128
#define NM 3136
#define NH 56
#define NW 56

// ---------------- scratch (static device globals; no runtime alloc) ----------
__device__ __align__(16) unsigned short g_yh[NB*ND*NM];  // relu(bn1(conv1)) bf16
__device__ __align__(16) unsigned short g_sh[NB*ND*NM];  // bn3(conv2) bf16
__device__ float g_ymean[NB*ND];                         // row sums of y (exact)
__device__ __align__(16) float g_cov[NB*ND*ND];          // raw y*y^T sums
__device__ __align__(16) float g_sp[NB*ND*64];           // 8x8 pooled s
__device__ float g_catt[NB*NC];
__device__ float g_patt[NB*64];
__device__ float g_vch[NB*512];
__device__ __align__(16) char  g_wa[32*12288];           // fp16 weights, smem layout

// ---------------- helpers ------------------------------------------------------
__device__ __forceinline__ uint32_t smem_u32(const void* p){
    uint32_t a;
    asm("{ .reg .u64 t; cvta.to.shared.u64 t, %1; cvt.u32.u64 %0, t; }" : "=r"(a) : "l"(p));
    return a;
}
__device__ __forceinline__ void cp16(uint32_t d, const void* s){
    asm volatile("cp.async.cg.shared.global [%0], [%1], 16;" :: "r"(d), "l"(s));
}
__device__ __forceinline__ void ldsm4(uint32_t* r, uint32_t a){
    asm volatile("ldmatrix.sync.aligned.m8n8.x4.shared.b16 {%0,%1,%2,%3}, [%4];"
        : "=r"(r[0]),"=r"(r[1]),"=r"(r[2]),"=r"(r[3]) : "r"(a));
}
__device__ __forceinline__ void ldsm4t(uint32_t* r, uint32_t a){
    asm volatile("ldmatrix.sync.aligned.m8n8.x4.trans.shared.b16 {%0,%1,%2,%3}, [%4];"
        : "=r"(r[0]),"=r"(r[1]),"=r"(r[2]),"=r"(r[3]) : "r"(a));
}
__device__ __forceinline__ void mma_bf16(float* c, const uint32_t* a, const uint32_t* b){
    asm volatile("mma.sync.aligned.m16n8k16.row.col.f32.bf16.bf16.f32 "
        "{%0,%1,%2,%3},{%4,%5,%6,%7},{%8,%9},{%0,%1,%2,%3};"
        : "+f"(c[0]),"+f"(c[1]),"+f"(c[2]),"+f"(c[3])
        : "r"(a[0]),"r"(a[1]),"r"(a[2]),"r"(a[3]), "r"(b[0]),"r"(b[1]));
}
__device__ __forceinline__ void mma_f16(float* c, const uint32_t* a, const uint32_t* b){
    asm volatile("mma.sync.aligned.m16n8k16.row.col.f32.f16.f16.f32 "
        "{%0,%1,%2,%3},{%4,%5,%6,%7},{%8,%9},{%0,%1,%2,%3};"
        : "+f"(c[0]),"+f"(c[1]),"+f"(c[2]),"+f"(c[3])
        : "r"(a[0]),"r"(a[1]),"r"(a[2]),"r"(a[3]), "r"(b[0]),"r"(b[1]));
}

// ---------------- zero scratch accumulators ----------------------------------
__global__ void k_zero(){
    int i = blockIdx.x*256 + threadIdx.x;
    if (i < NB*ND*ND) g_cov[i]   = 0.f;
    if (i < NB*ND)    g_ymean[i] = 0.f;
}

// ---------------- prep: weights -> single fp16 tiles in smem layout ------------
#define ACH   12288                 // bytes per chunk
#define A2ROW 48                    // bytes per A row (16 fp16 = 32B + 16B pad)
__global__ void k_prep_w(const float* __restrict__ wdr, const float* __restrict__ wdrs){
    const int c = blockIdx.x, row = threadIdx.x;
    const float* __restrict__ Wr = (row < 128) ? (wdr + row*NC) : (wdrs + (row-128)*NC);
    char* base = g_wa + c*ACH + row*A2ROW;
#pragma unroll
    for (int j=0;j<4;j++){
        float4 v = *(const float4*)(Wr + c*16 + j*4);
        ushort4 hv;
        hv.x = __half_as_ushort(__float2half_rn(v.x));
        hv.y = __half_as_ushort(__float2half_rn(v.y));
        hv.z = __half_as_ushort(__float2half_rn(v.z));
        hv.w = __half_as_ushort(__float2half_rn(v.w));
        *(ushort4*)(base + j*8) = hv;
    }
}

// =============== fused dual-conv, 256-thr CTAs, 2 CTAs/SM =====================
// grid (49, 32): x = 64-wide m tile (3136 = 49*64, no bounds checks), y = batch.
// 8 warps = 4(M) x 2(N); warp tile 64x32 over CTA tile 256x64.
#define BROW   144                  // bytes per B fp16 row (64 fp16 + 16B pad)
#define B16OFF ACH                  // 12288
#define B32OFF (ACH + 16*BROW)      // 14592
#define B32ROW 272                  // bytes per B fp32 staging row (256 + 16 pad)
#define CBUF   (B32OFF + 16*B32ROW) // 18944 per buffer
#define NBUFS  5

__global__ void __launch_bounds__(256,2) k_conv_mma(
    const float* __restrict__ x,
    const float* __restrict__ bdr,
    const float* __restrict__ g1,   const float* __restrict__ be1,
    const float* __restrict__ m1,   const float* __restrict__ v1,
    const float* __restrict__ bdrs,
    const float* __restrict__ g3,   const float* __restrict__ be3,
    const float* __restrict__ m3,   const float* __restrict__ v3)
{
    extern __shared__ char smem[];
    const uint32_t sb = smem_u32(smem);
    const int tid = threadIdx.x, l = tid & 31, w = tid >> 5;
    const int b = blockIdx.y, m0 = blockIdx.x*64;
    const int wm = w >> 1, wn = w & 1;
    const float* __restrict__ xb = x + (size_t)b * ((size_t)NC*NM);

    float acc[4][4][4];
#pragma unroll
    for (int i=0;i<4;i++)
#pragma unroll
        for (int j=0;j<4;j++)
#pragma unroll
            for (int k=0;k<4;k++) acc[i][j][k]=0.f;

    const int kkI = tid >> 4, segI = tid & 15;
    auto issue = [&](int c, int bidx){
        const uint32_t abase = sb + bidx*CBUF;
        const char* srcA = g_wa + c*ACH;
#pragma unroll
        for (int r=0;r<3;r++){
            uint32_t off = (uint32_t)((r*256 + tid)*16);
            cp16(abase + off, srcA + off);
        }
        const float* srcB = xb + (size_t)(c*16 + kkI)*NM + m0 + segI*4;
        cp16(abase + B32OFF + kkI*B32ROW + segI*16, srcB);
        asm volatile("cp.async.commit_group;" ::: "memory");
    };

    issue(0,0); issue(1,1); issue(2,2);
    int ibuf = 3, cbuf = 0;
    const int arow = wm*64 + (l&15);
    const int akb  = ((l&16)?16:0);
    for (int c = 0; c < 32; c++){
        if (c < 30)      asm volatile("cp.async.wait_group 2;" ::: "memory");
        else if (c==30)  asm volatile("cp.async.wait_group 1;" ::: "memory");
        else             asm volatile("cp.async.wait_group 0;" ::: "memory");
        if (c + 3 < 32){ issue(c+3, ibuf); if(++ibuf==NBUFS) ibuf=0; }
        const uint32_t abase = sb + cbuf*CBUF;
        // convert own B region fp32 -> relu fp16 (per-thread self-consistent)
        {
            char* bufp = smem + (abase - sb);
            float4 v = *(const float4*)(bufp + B32OFF + kkI*B32ROW + segI*16);
            __half2 h0 = __floats2half2_rn(fmaxf(v.x,0.f), fmaxf(v.y,0.f));
            __half2 h1 = __floats2half2_rn(fmaxf(v.z,0.f), fmaxf(v.w,0.f));
            uint2 o;
            o.x = *(uint32_t*)&h0;
            o.y = *(uint32_t*)&h1;
            *(uint2*)(bufp + B16OFF + kkI*BROW + segI*8) = o;
        }
        __syncthreads();
        uint32_t BH[4][2];
#pragma unroll
        for (int p=0;p<2;p++){
            int n0 = wn*32 + p*16 + ((l&16)?8:0);
            uint32_t bd = abase + B16OFF + (uint32_t)((l&15)*BROW + n0*2);
            uint32_t t4[4];
            ldsm4t(t4, bd);
            BH[2*p][0]=t4[0]; BH[2*p][1]=t4[1]; BH[2*p+1][0]=t4[2]; BH[2*p+1][1]=t4[3];
        }
#pragma unroll
        for (int mi=0;mi<4;mi++){
            uint32_t AH4[4];
            uint32_t ad = abase + (uint32_t)((arow + mi*16)*A2ROW) + akb;
            ldsm4(AH4, ad);
#pragma unroll
            for (int ni=0;ni<4;ni++)
                mma_f16(acc[mi][ni], AH4, BH[ni]);
        }
        if(++cbuf==NBUFS) cbuf=0;
    }

    // ---- epilogue: bias + BN (+relu) + store bf16 + row sums ----
    __syncthreads();
    const int r = l>>2, q = l&3;
#pragma unroll
    for (int mi=0;mi<4;mi++){
#pragma unroll
        for (int half=0; half<2; half++){
            int ar = wm*64 + mi*16 + r + half*8;     // 0..255
            int ot = ar >> 7;
            int o  = ar & 127;
            const float* gg = ot ? g3 : g1;
            const float* bb = ot ? be3 : be1;
            const float* mm = ot ? m3 : m1;
            const float* vv = ot ? v3 : v1;
            float bi2 = ot ? bdrs[o] : bdr[o];
            float sc = gg[o]*rsqrtf(vv[o]+EPSV);
            float ad = bi2*sc + bb[o] - mm[o]*sc;
            unsigned short* dst = (ot ? g_sh : g_yh) + (size_t)(b*ND + o)*NM;
            float rsum = 0.f;
#pragma unroll
            for (int ni=0;ni<4;ni++){
                int m = m0 + wn*32 + ni*8 + q*2;
                float v0 = acc[mi][ni][half*2+0]*sc + ad;
                float v1 = acc[mi][ni][half*2+1]*sc + ad;
                if (ot==0){
                    v0 = fmaxf(v0,0.f); v1 = fmaxf(v1,0.f);
                    rsum += v0 + v1;
                }
                __nv_bfloat162 h2 = __floats2bfloat162_rn(v0, v1);
                *(uint32_t*)(dst + m) = *(uint32_t*)&h2;
            }
            if (ot==0){
                rsum += __shfl_xor_sync(0xffffffffu, rsum, 1);
                rsum += __shfl_xor_sync(0xffffffffu, rsum, 2);
                if (q==0) atomicAdd(&g_ymean[b*ND + o], rsum);
            }
        }
    }
}

// =============== channel covariance, single-product bf16, 2 CTAs/SM ===========
#define CAROW 80
#define CTB   (128*CAROW)   // 10240 per buffer

__global__ void __launch_bounds__(256,2) k_cov_mma()
{
    extern __shared__ char smem[];
    const uint32_t sb = smem_u32(smem);
    const int tid = threadIdx.x, l = tid & 31, w = tid >> 5;
    const int b = blockIdx.y, kb = blockIdx.x*448;
    const int wr = w >> 2, wc = w & 3;
    const unsigned short* __restrict__ yb = g_yh + (size_t)b*ND*NM;

    float acc[4][4][4];
#pragma unroll
    for (int i=0;i<4;i++)
#pragma unroll
        for (int j=0;j<4;j++)
#pragma unroll
            for (int k=0;k<4;k++) acc[i][j][k]=0.f;

    uint4 py[2];
    auto ldg = [&](int c0){
#pragma unroll
        for (int r=0;r<2;r++){
            int idx = r*256+tid;
            int d = idx>>2, m8 = idx&3;
            py[r] = *(const uint4*)(yb + (size_t)d*NM + kb + c0 + m8*8);
        }
    };
    auto sts = [&](int buf){
        char* base = smem + buf*CTB;
#pragma unroll
        for (int r=0;r<2;r++){
            int idx = r*256+tid;
            int d = idx>>2, m8 = idx&3;
            *(uint4*)(base + d*CAROW + m8*16) = py[r];
        }
    };

    ldg(0); sts(0); ldg(32);
    __syncthreads();
    int buf = 0;
    const int arow = wr*64 + (l&15);
    const int brow = wc*32 + (l&15);
    const int akad = ((l&16)?8:0);
    for (int c = 0; c < 14; c++){
        uint32_t abase = sb + buf*CTB;
#pragma unroll
        for (int ks=0; ks<32; ks+=16){
            uint32_t AH[4][4], BH[4][2];
#pragma unroll
            for (int mi=0;mi<4;mi++){
                uint32_t ad = abase + (uint32_t)((arow + mi*16)*CAROW + (ks+akad)*2);
                ldsm4(AH[mi], ad);
            }
#pragma unroll
            for (int p=0;p<2;p++){
                uint32_t bd = abase + (uint32_t)((brow + p*16)*CAROW + (ks+akad)*2);
                uint32_t t4[4];
                ldsm4(t4, bd);
                BH[2*p][0]=t4[0]; BH[2*p][1]=t4[2]; BH[2*p+1][0]=t4[1]; BH[2*p+1][1]=t4[3];
            }
#pragma unroll
            for (int mi=0;mi<4;mi++)
#pragma unroll
                for (int ni=0;ni<4;ni++)
                    mma_bf16(acc[mi][ni], AH[mi], BH[ni]);
        }
        __syncthreads();
        if (c < 13){
            sts(buf^1);
            if (c < 12) ldg((c+2)*32);
            __syncthreads();
            buf ^= 1;
        }
    }

    float* cb = g_cov + (size_t)b*ND*ND;
    const int r = l>>2, q = l&3;
#pragma unroll
    for (int mi=0;mi<4;mi++){
#pragma unroll
        for (int half=0; half<2; half++){
            int ro = wr*64 + mi*16 + r + half*8;
#pragma unroll
            for (int ni=0;ni<4;ni++){
                int co = wc*32 + ni*8 + q*2;
                atomicAdd(&cb[ro*ND+co],   acc[mi][ni][half*2+0]);
                atomicAdd(&cb[ro*ND+co+1], acc[mi][ni][half*2+1]);
            }
        }
    }
}

// ---------------- 8x8 average pooling of s (bf16 input) -----------------------
__global__ void k_pool(){
    const int bd = blockIdx.x;
    const int t = threadIdx.x;
    __shared__ float sb[NM];
    const unsigned short* sp = g_sh + (size_t)bd*NM;
    for (int i=t;i<392;i+=256){
        uint4 v = ((const uint4*)sp)[i];
        float* d = sb + i*8;
        d[0] = __uint_as_float(v.x << 16);
        d[1] = __uint_as_float(v.x & 0xffff0000u);
        d[2] = __uint_as_float(v.y << 16);
        d[3] = __uint_as_float(v.y & 0xffff0000u);
        d[4] = __uint_as_float(v.z << 16);
        d[5] = __uint_as_float(v.z & 0xffff0000u);
        d[6] = __uint_as_float(v.w << 16);
        d[7] = __uint_as_float(v.w & 0xffff0000u);
    }
    __syncthreads();
    int cell = t>>2, sub = t&3;
    int gh = cell>>3, gw = cell&7;
    float sum = 0.f;
    for (int e = sub; e < 49; e += 4){
        int i = e/7, j = e-i*7;
        sum += sb[(gh*7+i)*NW + gw*7 + j];
    }
    sum += __shfl_xor_sync(0xffffffffu, sum, 1);
    sum += __shfl_xor_sync(0xffffffffu, sum, 2);
    if (sub==0) g_sp[bd*64+cell] = sum*(1.f/49.f);
}

// ---------------- channel attention, stage 1: vch -----------------------------
__global__ void k_catt1(const float* __restrict__ g2, const float* __restrict__ be2,
                        const float* __restrict__ m2, const float* __restrict__ v2,
                        const float* __restrict__ wrow, const float* __restrict__ brow)
{
    const int b = blockIdx.x, t = threadIdx.x;
    __shared__ float meanS[ND];
    if (t < ND) meanS[t] = g_ymean[b*ND+t] * (1.f/(float)NM);
    __syncthreads();
    int f = blockIdx.y*128 + t;
    int i = f>>2;
    float mi = meanS[i];
    float sc = g2[i]*rsqrtf(v2[i]+EPSV);
    float sh = be2[i] - m2[i]*sc;
    const float* cr = g_cov + (size_t)b*ND*ND + i*ND;
    const float* wr = wrow + f*ND;
    float acc = 0.f;
    for (int k=0;k<ND;k++){
        float cb = (cr[k]*(1.f/(float)NM) - mi*meanS[k])*sc + sh;
        acc += cb * wr[k];
    }
    g_vch[b*512+f] = acc + brow[f];
}

// ---------------- channel attention, stage 2: sigmoid(fc) ---------------------
__global__ void k_catt2(const float* __restrict__ wfc, const float* __restrict__ bfc)
{
    const int b = blockIdx.x, t = threadIdx.x;
    __shared__ float vchS[512];
#pragma unroll
    for (int r=0;r<4;r++) vchS[r*128+t] = g_vch[b*512 + r*128 + t];
    __syncthreads();
    int c = blockIdx.y*128 + t;
    const float* wf = wfc + c*512;
    float acc = bfc[c];
    for (int f=0; f<512; f++) acc += vchS[f]*wf[f];
    g_catt[b*512+c] = 1.f/(1.f+expf(-acc));
}

// ---------------- spatial attention -------------------------------------------
__global__ void k_patt(const float* __restrict__ g4, const float* __restrict__ be4,
                       const float* __restrict__ m4, const float* __restrict__ v4,
                       const float* __restrict__ wrows, const float* __restrict__ brows,
                       const float* __restrict__ wfcs,  const float* __restrict__ bfcs)
{
    const int b = blockIdx.x, t = threadIdx.x;
    __shared__ float sf[ND*64];
    __shared__ float cs[64];
    __shared__ float vsS[256];
    for (int i=t;i<ND*64;i+=256) sf[i] = g_sp[(size_t)b*ND*64 + i];
    __syncthreads();
    if (t<64){
        float s=0.f;
        for (int c=0;c<ND;c++) s += sf[c*64+t];
        cs[t]=s;
    }
    __syncthreads();
    const int tym = t>>4, txn = t&15;
    float a[4][4];
#pragma unroll
    for (int ii=0;ii<4;ii++)
#pragma unroll
        for (int jj=0;jj<4;jj++) a[ii][jj]=0.f;
    for (int c=0;c<ND;c++){
        const float* row = sf + c*64;
        float am[4], bv[4];
#pragma unroll
        for (int ii=0;ii<4;ii++) am[ii]=row[tym*4+ii];
#pragma unroll
        for (int jj=0;jj<4;jj++) bv[jj]=row[txn*4+jj];
#pragma unroll
        for (int ii=0;ii<4;ii++)
#pragma unroll
            for (int jj=0;jj<4;jj++) a[ii][jj] += am[ii]*bv[jj];
    }
    __syncthreads();
#pragma unroll
    for (int ii=0;ii<4;ii++){
        int m = tym*4+ii;
        float sc = g4[m]*rsqrtf(v4[m]+EPSV);
        float sh = be4[m] - m4[m]*sc;
        float cm = cs[m];
#pragma unroll
        for (int jj=0;jj<4;jj++){
            int n = txn*4+jj;
            float cv = (a[ii][jj] - cm*cs[n]*(1.f/64.f))*(1.f/64.f);
            sf[m*64+n] = cv*sc + sh;
        }
    }
    __syncthreads();
    {
        int f = t;
        int i = f>>2;
        const float* wr = wrows + f*64;
        float acc = brows[f];
        for (int k=0;k<64;k++) acc += sf[i*64+k]*wr[k];
        vsS[f] = fmaxf(acc, 0.f);
    }
    __syncthreads();
    if (t<64){
        const float* wf = wfcs + t*256;
        float acc = bfcs[t];
        for (int f=0;f<256;f++) acc += vsS[f]*wf[f];
        g_patt[b*64+t] = 1.f/(1.f+expf(-acc));
    }
}

// ---------------- final: out = x*catt + relu(x*patt) --------------------------
__global__ void k_final(const float* __restrict__ x, float* __restrict__ out){
    unsigned idx = (blockIdx.x*256u + threadIdx.x)*4u;
    unsigned bc  = idx / (unsigned)NM;
    unsigned pos = idx - bc*(unsigned)NM;
    unsigned b   = bc >> 9;
    unsigned h   = pos / (unsigned)NW;
    unsigned w   = pos - h*(unsigned)NW;
    float catt = g_catt[bc];
    const float* prow = g_patt + b*64u + (h/7u)*8u;
    float4 xv = *(const float4*)(x + idx);
    float p0 = prow[(w+0u)/7u];
    float p1 = prow[(w+1u)/7u];
    float p2 = prow[(w+2u)/7u];
    float p3 = prow[(w+3u)/7u];
    float4 o;
    o.x = xv.x*catt + fmaxf(xv.x*p0, 0.f);
    o.y = xv.y*catt + fmaxf(xv.y*p1, 0.f);
    o.z = xv.z*catt + fmaxf(xv.z*p2, 0.f);
    o.w = xv.w*catt + fmaxf(xv.w*p3, 0.f);
    *(float4*)(out + idx) = o;
}

// ---------------- launch ------------------------------------------------------
extern "C" void kernel_launch(void* const* d_in, const int* in_sizes, int n_in,
                              void* d_out, int out_size)
{
    (void)in_sizes; (void)n_in; (void)out_size;
    const float* x     = (const float*)d_in[0];
    const float* wdr   = (const float*)d_in[1];
    const float* bdr   = (const float*)d_in[2];
    const float* g1    = (const float*)d_in[3];
    const float* be1   = (const float*)d_in[4];
    const float* m1    = (const float*)d_in[5];
    const float* v1    = (const float*)d_in[6];
    const float* g2    = (const float*)d_in[7];
    const float* be2   = (const float*)d_in[8];
    const float* m2    = (const float*)d_in[9];
    const float* v2    = (const float*)d_in[10];
    const float* wrow  = (const float*)d_in[11];
    const float* brow  = (const float*)d_in[12];
    const float* wfc   = (const float*)d_in[13];
    const float* bfc   = (const float*)d_in[14];
    const float* wdrs  = (const float*)d_in[15];
    const float* bdrs  = (const float*)d_in[16];
    const float* g3    = (const float*)d_in[17];
    const float* be3   = (const float*)d_in[18];
    const float* m3    = (const float*)d_in[19];
    const float* v3    = (const float*)d_in[20];
    const float* g4    = (const float*)d_in[21];
    const float* be4   = (const float*)d_in[22];
    const float* m4    = (const float*)d_in[23];
    const float* v4    = (const float*)d_in[24];
    const float* wrows = (const float*)d_in[25];
    const float* brows = (const float*)d_in[26];
    const float* wfcs  = (const float*)d_in[27];
    const float* bfcs  = (const float*)d_in[28];
    float* out = (float*)d_out;

    cudaFuncSetAttribute(k_conv_mma, cudaFuncAttributeMaxDynamicSharedMemorySize, NBUFS*CBUF);
    cudaFuncSetAttribute(k_cov_mma,  cudaFuncAttributeMaxDynamicSharedMemorySize, 2*CTB);

    k_zero<<<2048, 256>>>();
    k_prep_w<<<32, 256>>>(wdr, wdrs);
    k_prep_w<<<32, 256>>>(wdr, wdrs);   // idempotent; keeps conv in profiled slot 4
    dim3 gconv(49, 32);
    k_conv_mma<<<gconv, 256, NBUFS*CBUF>>>(x, bdr, g1, be1, m1, v1,
                                           bdrs, g3, be3, m3, v3);
    dim3 gcov(7, 32);
    k_cov_mma<<<gcov, 256, 2*CTB>>>();
    k_pool<<<4096, 256>>>();
    dim3 gcatt(32, 4);
    k_catt1<<<gcatt, 128>>>(g2, be2, m2, v2, wrow, brow);
    k_catt2<<<gcatt, 128>>>(wfc, bfc);
    k_patt<<<32, 256>>>(g4, be4, m4, v4, wrows, brows, wfcs, bfcs);
    k_final<<<50176, 256>>>(x, out);
}

// round 17
// speedup vs baseline: 1.0183x; 1.0183x over previous
#include <cuda_runtime.h>
#include <cuda_bf16.h>
#include <cuda_fp16.h>
#include <cstdint>

#define EPSV 1e-5f

#define NB 32
#define NC 512
#define ND 128
#define NM 3136
#define NH 56
#define NW 56

// ---------------- scratch (static device globals; no runtime alloc) ----------
__device__ __align__(16) unsigned short g_yh[NB*ND*NM];  // relu(bn1(conv1)) bf16
__device__ __align__(16) unsigned short g_sh[NB*ND*NM];  // bn3(conv2) bf16
__device__ float g_ymean[NB*ND];                         // row sums of y (exact)
__device__ __align__(16) float g_cov[NB*ND*ND];          // raw y*y^T sums
__device__ __align__(16) float g_sp[NB*ND*64];           // 8x8 pooled s
__device__ float g_catt[NB*NC];
__device__ float g_patt[NB*64];
__device__ float g_vch[NB*512];
__device__ __align__(16) char  g_wa[32*12288];           // fp16 weights, smem layout

// ---------------- helpers ------------------------------------------------------
__device__ __forceinline__ uint32_t smem_u32(const void* p){
    uint32_t a;
    asm("{ .reg .u64 t; cvta.to.shared.u64 t, %1; cvt.u32.u64 %0, t; }" : "=r"(a) : "l"(p));
    return a;
}
__device__ __forceinline__ void cp16(uint32_t d, const void* s){
    asm volatile("cp.async.cg.shared.global [%0], [%1], 16;" :: "r"(d), "l"(s));
}
__device__ __forceinline__ void ldsm4(uint32_t* r, uint32_t a){
    asm volatile("ldmatrix.sync.aligned.m8n8.x4.shared.b16 {%0,%1,%2,%3}, [%4];"
        : "=r"(r[0]),"=r"(r[1]),"=r"(r[2]),"=r"(r[3]) : "r"(a));
}
__device__ __forceinline__ void ldsm4t(uint32_t* r, uint32_t a){
    asm volatile("ldmatrix.sync.aligned.m8n8.x4.trans.shared.b16 {%0,%1,%2,%3}, [%4];"
        : "=r"(r[0]),"=r"(r[1]),"=r"(r[2]),"=r"(r[3]) : "r"(a));
}
__device__ __forceinline__ void mma_bf16(float* c, const uint32_t* a, const uint32_t* b){
    asm volatile("mma.sync.aligned.m16n8k16.row.col.f32.bf16.bf16.f32 "
        "{%0,%1,%2,%3},{%4,%5,%6,%7},{%8,%9},{%0,%1,%2,%3};"
        : "+f"(c[0]),"+f"(c[1]),"+f"(c[2]),"+f"(c[3])
        : "r"(a[0]),"r"(a[1]),"r"(a[2]),"r"(a[3]), "r"(b[0]),"r"(b[1]));
}
__device__ __forceinline__ void mma_f16(float* c, const uint32_t* a, const uint32_t* b){
    asm volatile("mma.sync.aligned.m16n8k16.row.col.f32.f16.f16.f32 "
        "{%0,%1,%2,%3},{%4,%5,%6,%7},{%8,%9},{%0,%1,%2,%3};"
        : "+f"(c[0]),"+f"(c[1]),"+f"(c[2]),"+f"(c[3])
        : "r"(a[0]),"r"(a[1]),"r"(a[2]),"r"(a[3]), "r"(b[0]),"r"(b[1]));
}

// ---------------- zero scratch accumulators ----------------------------------
__global__ void k_zero(){
    int i = blockIdx.x*256 + threadIdx.x;
    if (i < NB*ND*ND) g_cov[i]   = 0.f;
    if (i < NB*ND)    g_ymean[i] = 0.f;
}

// ---------------- prep: weights -> single fp16 tiles in smem layout ------------
#define ACH   12288                 // bytes per chunk
#define A2ROW 48                    // bytes per A row (16 fp16 = 32B + 16B pad)
__global__ void k_prep_w(const float* __restrict__ wdr, const float* __restrict__ wdrs){
    const int c = blockIdx.x, row = threadIdx.x;
    const float* __restrict__ Wr = (row < 128) ? (wdr + row*NC) : (wdrs + (row-128)*NC);
    char* base = g_wa + c*ACH + row*A2ROW;
#pragma unroll
    for (int j=0;j<4;j++){
        float4 v = *(const float4*)(Wr + c*16 + j*4);
        ushort4 hv;
        hv.x = __half_as_ushort(__float2half_rn(v.x));
        hv.y = __half_as_ushort(__float2half_rn(v.y));
        hv.z = __half_as_ushort(__float2half_rn(v.z));
        hv.w = __half_as_ushort(__float2half_rn(v.w));
        *(ushort4*)(base + j*8) = hv;
    }
}

// =============== fused dual-conv, 256-thr CTAs, 2 CTAs/SM =====================
// grid (49, 32): x = 64-wide m tile (3136 = 49*64, no bounds checks), y = batch.
// 8 warps = 4(M) x 2(N); warp tile 64x32 over CTA tile 256x64.
#define BROW   144                  // bytes per B fp16 row (64 fp16 + 16B pad)
#define B16OFF ACH                  // 12288
#define B32OFF (ACH + 16*BROW)      // 14592
#define B32ROW 272                  // bytes per B fp32 staging row (256 + 16 pad)
#define CBUF   (B32OFF + 16*B32ROW) // 18944 per buffer
#define NBUFS  5

__global__ void __launch_bounds__(256,2) k_conv_mma(
    const float* __restrict__ x,
    const float* __restrict__ bdr,
    const float* __restrict__ g1,   const float* __restrict__ be1,
    const float* __restrict__ m1,   const float* __restrict__ v1,
    const float* __restrict__ bdrs,
    const float* __restrict__ g3,   const float* __restrict__ be3,
    const float* __restrict__ m3,   const float* __restrict__ v3)
{
    extern __shared__ char smem[];
    const uint32_t sb = smem_u32(smem);
    const int tid = threadIdx.x, l = tid & 31, w = tid >> 5;
    const int b = blockIdx.y, m0 = blockIdx.x*64;
    const int wm = w >> 1, wn = w & 1;
    const float* __restrict__ xb = x + (size_t)b * ((size_t)NC*NM);

    float acc[4][4][4];
#pragma unroll
    for (int i=0;i<4;i++)
#pragma unroll
        for (int j=0;j<4;j++)
#pragma unroll
            for (int k=0;k<4;k++) acc[i][j][k]=0.f;

    const int kkI = tid >> 4, segI = tid & 15;
    auto issue = [&](int c, int bidx){
        const uint32_t abase = sb + bidx*CBUF;
        const char* srcA = g_wa + c*ACH;
#pragma unroll
        for (int r=0;r<3;r++){
            uint32_t off = (uint32_t)((r*256 + tid)*16);
            cp16(abase + off, srcA + off);
        }
        const float* srcB = xb + (size_t)(c*16 + kkI)*NM + m0 + segI*4;
        cp16(abase + B32OFF + kkI*B32ROW + segI*16, srcB);
        asm volatile("cp.async.commit_group;" ::: "memory");
    };

    issue(0,0); issue(1,1); issue(2,2);
    int ibuf = 3, cbuf = 0;
    const int arow = wm*64 + (l&15);
    const int akb  = ((l&16)?16:0);
    for (int c = 0; c < 32; c++){
        if (c < 30)      asm volatile("cp.async.wait_group 2;" ::: "memory");
        else if (c==30)  asm volatile("cp.async.wait_group 1;" ::: "memory");
        else             asm volatile("cp.async.wait_group 0;" ::: "memory");
        if (c + 3 < 32){ issue(c+3, ibuf); if(++ibuf==NBUFS) ibuf=0; }
        const uint32_t abase = sb + cbuf*CBUF;
        // convert own B region fp32 -> relu fp16 (per-thread self-consistent)
        {
            char* bufp = smem + (abase - sb);
            float4 v = *(const float4*)(bufp + B32OFF + kkI*B32ROW + segI*16);
            __half2 h0 = __floats2half2_rn(fmaxf(v.x,0.f), fmaxf(v.y,0.f));
            __half2 h1 = __floats2half2_rn(fmaxf(v.z,0.f), fmaxf(v.w,0.f));
            uint2 o;
            o.x = *(uint32_t*)&h0;
            o.y = *(uint32_t*)&h1;
            *(uint2*)(bufp + B16OFF + kkI*BROW + segI*8) = o;
        }
        __syncthreads();
        uint32_t BH[4][2];
#pragma unroll
        for (int p=0;p<2;p++){
            int n0 = wn*32 + p*16 + ((l&16)?8:0);
            uint32_t bd = abase + B16OFF + (uint32_t)((l&15)*BROW + n0*2);
            uint32_t t4[4];
            ldsm4t(t4, bd);
            BH[2*p][0]=t4[0]; BH[2*p][1]=t4[1]; BH[2*p+1][0]=t4[2]; BH[2*p+1][1]=t4[3];
        }
#pragma unroll
        for (int mi=0;mi<4;mi++){
            uint32_t AH4[4];
            uint32_t ad = abase + (uint32_t)((arow + mi*16)*A2ROW) + akb;
            ldsm4(AH4, ad);
#pragma unroll
            for (int ni=0;ni<4;ni++)
                mma_f16(acc[mi][ni], AH4, BH[ni]);
        }
        if(++cbuf==NBUFS) cbuf=0;
    }

    // ---- epilogue: bias + BN (+relu) + store bf16 + row sums ----
    __syncthreads();
    const int r = l>>2, q = l&3;
#pragma unroll
    for (int mi=0;mi<4;mi++){
#pragma unroll
        for (int half=0; half<2; half++){
            int ar = wm*64 + mi*16 + r + half*8;     // 0..255
            int ot = ar >> 7;
            int o  = ar & 127;
            const float* gg = ot ? g3 : g1;
            const float* bb = ot ? be3 : be1;
            const float* mm = ot ? m3 : m1;
            const float* vv = ot ? v3 : v1;
            float bi2 = ot ? bdrs[o] : bdr[o];
            float sc = gg[o]*rsqrtf(vv[o]+EPSV);
            float ad = bi2*sc + bb[o] - mm[o]*sc;
            unsigned short* dst = (ot ? g_sh : g_yh) + (size_t)(b*ND + o)*NM;
            float rsum = 0.f;
#pragma unroll
            for (int ni=0;ni<4;ni++){
                int m = m0 + wn*32 + ni*8 + q*2;
                float v0 = acc[mi][ni][half*2+0]*sc + ad;
                float v1 = acc[mi][ni][half*2+1]*sc + ad;
                if (ot==0){
                    v0 = fmaxf(v0,0.f); v1 = fmaxf(v1,0.f);
                    rsum += v0 + v1;
                }
                __nv_bfloat162 h2 = __floats2bfloat162_rn(v0, v1);
                *(uint32_t*)(dst + m) = *(uint32_t*)&h2;
            }
            if (ot==0){
                rsum += __shfl_xor_sync(0xffffffffu, rsum, 1);
                rsum += __shfl_xor_sync(0xffffffffu, rsum, 2);
                if (q==0) atomicAdd(&g_ymean[b*ND + o], rsum);
            }
        }
    }
}

// =============== channel covariance, single-product bf16 ======================
#define CAROW 80
#define CTB   (128*CAROW)   // 10240 per buffer

__global__ void __launch_bounds__(256,1) k_cov_mma()
{
    extern __shared__ char smem[];
    const uint32_t sb = smem_u32(smem);
    const int tid = threadIdx.x, l = tid & 31, w = tid >> 5;
    const int b = blockIdx.y, kb = blockIdx.x*448;
    const int wr = w >> 2, wc = w & 3;
    const unsigned short* __restrict__ yb = g_yh + (size_t)b*ND*NM;

    float acc[4][4][4];
#pragma unroll
    for (int i=0;i<4;i++)
#pragma unroll
        for (int j=0;j<4;j++)
#pragma unroll
            for (int k=0;k<4;k++) acc[i][j][k]=0.f;

    uint4 py[2];
    auto ldg = [&](int c0){
#pragma unroll
        for (int r=0;r<2;r++){
            int idx = r*256+tid;
            int d = idx>>2, m8 = idx&3;
            py[r] = *(const uint4*)(yb + (size_t)d*NM + kb + c0 + m8*8);
        }
    };
    auto sts = [&](int buf){
        char* base = smem + buf*CTB;
#pragma unroll
        for (int r=0;r<2;r++){
            int idx = r*256+tid;
            int d = idx>>2, m8 = idx&3;
            *(uint4*)(base + d*CAROW + m8*16) = py[r];
        }
    };

    ldg(0); sts(0); ldg(32);
    __syncthreads();
    int buf = 0;
    const int arow = wr*64 + (l&15);
    const int brow = wc*32 + (l&15);
    const int akad = ((l&16)?8:0);
    for (int c = 0; c < 14; c++){
        uint32_t abase = sb + buf*CTB;
#pragma unroll
        for (int ks=0; ks<32; ks+=16){
            uint32_t AH[4][4], BH[4][2];
#pragma unroll
            for (int mi=0;mi<4;mi++){
                uint32_t ad = abase + (uint32_t)((arow + mi*16)*CAROW + (ks+akad)*2);
                ldsm4(AH[mi], ad);
            }
#pragma unroll
            for (int p=0;p<2;p++){
                uint32_t bd = abase + (uint32_t)((brow + p*16)*CAROW + (ks+akad)*2);
                uint32_t t4[4];
                ldsm4(t4, bd);
                BH[2*p][0]=t4[0]; BH[2*p][1]=t4[2]; BH[2*p+1][0]=t4[1]; BH[2*p+1][1]=t4[3];
            }
#pragma unroll
            for (int mi=0;mi<4;mi++)
#pragma unroll
                for (int ni=0;ni<4;ni++)
                    mma_bf16(acc[mi][ni], AH[mi], BH[ni]);
        }
        __syncthreads();
        if (c < 13){
            sts(buf^1);
            if (c < 12) ldg((c+2)*32);
            __syncthreads();
            buf ^= 1;
        }
    }

    float* cb = g_cov + (size_t)b*ND*ND;
    const int r = l>>2, q = l&3;
#pragma unroll
    for (int mi=0;mi<4;mi++){
#pragma unroll
        for (int half=0; half<2; half++){
            int ro = wr*64 + mi*16 + r + half*8;
#pragma unroll
            for (int ni=0;ni<4;ni++){
                int co = wc*32 + ni*8 + q*2;
                atomicAdd(&cb[ro*ND+co],   acc[mi][ni][half*2+0]);
                atomicAdd(&cb[ro*ND+co+1], acc[mi][ni][half*2+1]);
            }
        }
    }
}

// ---------------- 8x8 average pooling of s (bf16 input) -----------------------
__global__ void k_pool(){
    const int bd = blockIdx.x;
    const int t = threadIdx.x;
    __shared__ float sb[NM];
    const unsigned short* sp = g_sh + (size_t)bd*NM;
    for (int i=t;i<392;i+=256){
        uint4 v = ((const uint4*)sp)[i];
        float* d = sb + i*8;
        d[0] = __uint_as_float(v.x << 16);
        d[1] = __uint_as_float(v.x & 0xffff0000u);
        d[2] = __uint_as_float(v.y << 16);
        d[3] = __uint_as_float(v.y & 0xffff0000u);
        d[4] = __uint_as_float(v.z << 16);
        d[5] = __uint_as_float(v.z & 0xffff0000u);
        d[6] = __uint_as_float(v.w << 16);
        d[7] = __uint_as_float(v.w & 0xffff0000u);
    }
    __syncthreads();
    int cell = t>>2, sub = t&3;
    int gh = cell>>3, gw = cell&7;
    float sum = 0.f;
    for (int e = sub; e < 49; e += 4){
        int i = e/7, j = e-i*7;
        sum += sb[(gh*7+i)*NW + gw*7 + j];
    }
    sum += __shfl_xor_sync(0xffffffffu, sum, 1);
    sum += __shfl_xor_sync(0xffffffffu, sum, 2);
    if (sub==0) g_sp[bd*64+cell] = sum*(1.f/49.f);
}

// ---------------- channel attention, stage 1: vch -----------------------------
__global__ void k_catt1(const float* __restrict__ g2, const float* __restrict__ be2,
                        const float* __restrict__ m2, const float* __restrict__ v2,
                        const float* __restrict__ wrow, const float* __restrict__ brow)
{
    const int b = blockIdx.x, t = threadIdx.x;
    __shared__ float meanS[ND];
    if (t < ND) meanS[t] = g_ymean[b*ND+t] * (1.f/(float)NM);
    __syncthreads();
    int f = blockIdx.y*128 + t;
    int i = f>>2;
    float mi = meanS[i];
    float sc = g2[i]*rsqrtf(v2[i]+EPSV);
    float sh = be2[i] - m2[i]*sc;
    const float* cr = g_cov + (size_t)b*ND*ND + i*ND;
    const float* wr = wrow + f*ND;
    float acc = 0.f;
    for (int k=0;k<ND;k++){
        float cb = (cr[k]*(1.f/(float)NM) - mi*meanS[k])*sc + sh;
        acc += cb * wr[k];
    }
    g_vch[b*512+f] = acc + brow[f];
}

// ---------------- channel attention, stage 2: sigmoid(fc) ---------------------
__global__ void k_catt2(const float* __restrict__ wfc, const float* __restrict__ bfc)
{
    const int b = blockIdx.x, t = threadIdx.x;
    __shared__ float vchS[512];
#pragma unroll
    for (int r=0;r<4;r++) vchS[r*128+t] = g_vch[b*512 + r*128 + t];
    __syncthreads();
    int c = blockIdx.y*128 + t;
    const float* wf = wfc + c*512;
    float acc = bfc[c];
    for (int f=0; f<512; f++) acc += vchS[f]*wf[f];
    g_catt[b*512+c] = 1.f/(1.f+expf(-acc));
}

// ---------------- spatial attention -------------------------------------------
__global__ void k_patt(const float* __restrict__ g4, const float* __restrict__ be4,
                       const float* __restrict__ m4, const float* __restrict__ v4,
                       const float* __restrict__ wrows, const float* __restrict__ brows,
                       const float* __restrict__ wfcs,  const float* __restrict__ bfcs)
{
    const int b = blockIdx.x, t = threadIdx.x;
    __shared__ float sf[ND*64];
    __shared__ float cs[64];
    __shared__ float vsS[256];
    for (int i=t;i<ND*64;i+=256) sf[i] = g_sp[(size_t)b*ND*64 + i];
    __syncthreads();
    if (t<64){
        float s=0.f;
        for (int c=0;c<ND;c++) s += sf[c*64+t];
        cs[t]=s;
    }
    __syncthreads();
    const int tym = t>>4, txn = t&15;
    float a[4][4];
#pragma unroll
    for (int ii=0;ii<4;ii++)
#pragma unroll
        for (int jj=0;jj<4;jj++) a[ii][jj]=0.f;
    for (int c=0;c<ND;c++){
        const float* row = sf + c*64;
        float am[4], bv[4];
#pragma unroll
        for (int ii=0;ii<4;ii++) am[ii]=row[tym*4+ii];
#pragma unroll
        for (int jj=0;jj<4;jj++) bv[jj]=row[txn*4+jj];
#pragma unroll
        for (int ii=0;ii<4;ii++)
#pragma unroll
            for (int jj=0;jj<4;jj++) a[ii][jj] += am[ii]*bv[jj];
    }
    __syncthreads();
#pragma unroll
    for (int ii=0;ii<4;ii++){
        int m = tym*4+ii;
        float sc = g4[m]*rsqrtf(v4[m]+EPSV);
        float sh = be4[m] - m4[m]*sc;
        float cm = cs[m];
#pragma unroll
        for (int jj=0;jj<4;jj++){
            int n = txn*4+jj;
            float cv = (a[ii][jj] - cm*cs[n]*(1.f/64.f))*(1.f/64.f);
            sf[m*64+n] = cv*sc + sh;
        }
    }
    __syncthreads();
    {
        int f = t;
        int i = f>>2;
        const float* wr = wrows + f*64;
        float acc = brows[f];
        for (int k=0;k<64;k++) acc += sf[i*64+k]*wr[k];
        vsS[f] = fmaxf(acc, 0.f);
    }
    __syncthreads();
    if (t<64){
        const float* wf = wfcs + t*256;
        float acc = bfcs[t];
        for (int f=0;f<256;f++) acc += vsS[f]*wf[f];
        g_patt[b*64+t] = 1.f/(1.f+expf(-acc));
    }
}

// ---------------- final: out = x*catt + relu(x*patt) --------------------------
__global__ void k_final(const float* __restrict__ x, float* __restrict__ out){
    unsigned idx = (blockIdx.x*256u + threadIdx.x)*4u;
    unsigned bc  = idx / (unsigned)NM;
    unsigned pos = idx - bc*(unsigned)NM;
    unsigned b   = bc >> 9;
    unsigned h   = pos / (unsigned)NW;
    unsigned w   = pos - h*(unsigned)NW;
    float catt = g_catt[bc];
    const float* prow = g_patt + b*64u + (h/7u)*8u;
    float4 xv = *(const float4*)(x + idx);
    float p0 = prow[(w+0u)/7u];
    float p1 = prow[(w+1u)/7u];
    float p2 = prow[(w+2u)/7u];
    float p3 = prow[(w+3u)/7u];
    float4 o;
    o.x = xv.x*catt + fmaxf(xv.x*p0, 0.f);
    o.y = xv.y*catt + fmaxf(xv.y*p1, 0.f);
    o.z = xv.z*catt + fmaxf(xv.z*p2, 0.f);
    o.w = xv.w*catt + fmaxf(xv.w*p3, 0.f);
    *(float4*)(out + idx) = o;
}

// ---------------- launch ------------------------------------------------------
extern "C" void kernel_launch(void* const* d_in, const int* in_sizes, int n_in,
                              void* d_out, int out_size)
{
    (void)in_sizes; (void)n_in; (void)out_size;
    const float* x     = (const float*)d_in[0];
    const float* wdr   = (const float*)d_in[1];
    const float* bdr   = (const float*)d_in[2];
    const float* g1    = (const float*)d_in[3];
    const float* be1   = (const float*)d_in[4];
    const float* m1    = (const float*)d_in[5];
    const float* v1    = (const float*)d_in[6];
    const float* g2    = (const float*)d_in[7];
    const float* be2   = (const float*)d_in[8];
    const float* m2    = (const float*)d_in[9];
    const float* v2    = (const float*)d_in[10];
    const float* wrow  = (const float*)d_in[11];
    const float* brow  = (const float*)d_in[12];
    const float* wfc   = (const float*)d_in[13];
    const float* bfc   = (const float*)d_in[14];
    const float* wdrs  = (const float*)d_in[15];
    const float* bdrs  = (const float*)d_in[16];
    const float* g3    = (const float*)d_in[17];
    const float* be3   = (const float*)d_in[18];
    const float* m3    = (const float*)d_in[19];
    const float* v3    = (const float*)d_in[20];
    const float* g4    = (const float*)d_in[21];
    const float* be4   = (const float*)d_in[22];
    const float* m4    = (const float*)d_in[23];
    const float* v4    = (const float*)d_in[24];
    const float* wrows = (const float*)d_in[25];
    const float* brows = (const float*)d_in[26];
    const float* wfcs  = (const float*)d_in[27];
    const float* bfcs  = (const float*)d_in[28];
    float* out = (float*)d_out;

    cudaFuncSetAttribute(k_conv_mma, cudaFuncAttributeMaxDynamicSharedMemorySize, NBUFS*CBUF);
    cudaFuncSetAttribute(k_cov_mma,  cudaFuncAttributeMaxDynamicSharedMemorySize, 2*CTB);

    k_zero<<<2048, 256>>>();
    k_prep_w<<<32, 256>>>(wdr, wdrs);
    dim3 gconv(49, 32);
    k_conv_mma<<<gconv, 256, NBUFS*CBUF>>>(x, bdr, g1, be1, m1, v1,
                                           bdrs, g3, be3, m3, v3);
    dim3 gcov(7, 32);
    k_cov_mma<<<gcov, 256, 2*CTB>>>();
    k_pool<<<4096, 256>>>();
    dim3 gcatt(32, 4);
    k_catt1<<<gcatt, 128>>>(g2, be2, m2, v2, wrow, brow);
    k_catt2<<<gcatt, 128>>>(wfc, bfc);
    k_patt<<<32, 256>>>(g4, be4, m4, v4, wrows, brows, wfcs, bfcs);
    k_final<<<50176, 256>>>(x, out);
}